// round 16
// baseline (speedup 1.0000x reference)
#include <cuda_runtime.h>
#include <stdint.h>
#include <math.h>

#define BATCH 32
#define NBOX  10647          // 507 + 2028 + 8112
#define NBPAD 10648          // padded stride (16B-aligned uint4 rows)
#define KTOP  512
#define NBIN  4096
#define NCLS  80
#define CCAP  64             // per-class bucket capacity (avg 6.4, P(>64)~0)
#define TTOT  (BATCH * 3 * (169 + 676 + 2704))
#define T13   (BATCH * 3 * 169)
#define T26   (BATCH * 3 * 676)

// ---------------- scratch (no allocation allowed) ----------------
__device__ float    g_boxes[BATCH * NBOX * 8];  // x1,y1,x2,y2,conf,cls,pad,pad
__device__ unsigned g_skey [BATCH * NBPAD];     // mono32(score); pad elem stays 0
__device__ int      g_hist [BATCH * NBIN];      // zero at rest; decode fills, nms clears

__device__ __forceinline__ float sigm(float x) {
    return 1.0f / (1.0f + expf(-x));
}

// ---------------- compile-time specialized per-scale decode -------
template <int HW, int W, int NOFF>
__device__ __forceinline__ void decode_scale(const float* __restrict__ src,
                                             const float* __restrict__ anc,
                                             int r, float t)
{
    int b    = r / (3 * HW);
    int q    = r - b * 3 * HW;
    int a    = q / HW;
    int cell = q - a * HW;
    int y    = cell / W;
    int x    = cell - y * W;

    const float* p = src + ((size_t)b * 255 + (size_t)a * 85) * HW + cell;

    float tx = __ldcs(p);
    float ty = __ldcs(p + HW);
    float tw = __ldcs(p + 2 * HW);
    float th = __ldcs(p + 3 * HW);
    float to = __ldcs(p + 4 * HW);

    // argmax over 80 classes, pairwise-tree per group of 8 (first-occurrence ties)
    const float* pc = p + 5 * HW;
    float best = -3.402823466e38f;
    int   bcls = 0;
    #pragma unroll
    for (int f = 0; f < 80; f += 8) {
        float v0 = __ldcs(pc + (f + 0) * HW);
        float v1 = __ldcs(pc + (f + 1) * HW);
        float v2 = __ldcs(pc + (f + 2) * HW);
        float v3 = __ldcs(pc + (f + 3) * HW);
        float v4 = __ldcs(pc + (f + 4) * HW);
        float v5 = __ldcs(pc + (f + 5) * HW);
        float v6 = __ldcs(pc + (f + 6) * HW);
        float v7 = __ldcs(pc + (f + 7) * HW);
        float m01v = (v1 > v0) ? v1 : v0;  int m01i = (v1 > v0) ? f + 1 : f + 0;
        float m23v = (v3 > v2) ? v3 : v2;  int m23i = (v3 > v2) ? f + 3 : f + 2;
        float m45v = (v5 > v4) ? v5 : v4;  int m45i = (v5 > v4) ? f + 5 : f + 4;
        float m67v = (v7 > v6) ? v7 : v6;  int m67i = (v7 > v6) ? f + 7 : f + 6;
        float a03v = (m23v > m01v) ? m23v : m01v;  int a03i = (m23v > m01v) ? m23i : m01i;
        float a47v = (m67v > m45v) ? m67v : m45v;  int a47i = (m67v > m45v) ? m67i : m45i;
        float gv   = (a47v > a03v) ? a47v : a03v;  int gi   = (a47v > a03v) ? a47i : a03i;
        if (gv > best) { best = gv; bcls = gi; }
    }

    float conf = sigm(to);
    float cx   = ((float)x + sigm(tx)) * t;
    float cy   = ((float)y + sigm(ty)) * t;
    float w_   = anc[a * 2 + 0] * expf(tw);
    float h_   = anc[a * 2 + 1] * expf(th);

    int n = NOFF + cell * 3 + a;
    float4* bp = (float4*)(g_boxes + ((size_t)b * NBOX + n) * 8);
    __stcs(bp,     make_float4(cx - 0.5f * w_, cy - 0.5f * h_, cx + 0.5f * w_, cy + 0.5f * h_));
    __stcs(bp + 1, make_float4(conf, (float)bcls, 0.0f, 0.0f));

    unsigned sk = (conf > 0.5f) ? (__float_as_uint(conf) | 0x80000000u) : 0x407FFFFFu;
    g_skey[(size_t)b * NBPAD + n] = sk;
    if (conf > 0.5f)
        atomicAdd(&g_hist[b * NBIN + ((sk >> 11) & 0xFFFu)], 1);
}

__global__ void __launch_bounds__(256)
decode_all_kernel(const float* __restrict__ o13, const float* __restrict__ o26,
                  const float* __restrict__ o52, const float* __restrict__ a13,
                  const float* __restrict__ a26, const float* __restrict__ a52)
{
    int gid = blockIdx.x * blockDim.x + threadIdx.x;
    if (gid >= TTOT) return;

    if (gid < T13)
        decode_scale<169, 13, 0>(o13, a13, gid, 32.0f);
    else if (gid < T13 + T26)
        decode_scale<676, 26, 507>(o26, a26, gid - T13, 16.0f);
    else
        decode_scale<2704, 52, 2535>(o52, a52, gid - T13 - T26, 8.0f);
}

// ======== fused tail: hist-load + cumsum + scatter + rank/gather(+buckets)
//          + sup + greedy + coalesced output ======
// dyn smem (sequential lifetimes):
//   [0,16384)      hist int[4096]     } live until end of rank
//   [16384,32768)  cum  int[4096]     }
//   [32768,49152)  cumw int[4096]     } cumw dead after scatter
//   [49152,57344)  sel  u64[1024]
//   after scatter: cls_list u16[80*64] overlays [32768,43008)
//   after rank:    sup u32[512*16] overlays [0,32768)
#define K2_SMEM 57344

__global__ void __launch_bounds__(1024, 1)
nms_kernel(float* __restrict__ out)
{
    extern __shared__ char dyn[];
    int*                hist = (int*)dyn;
    int*                cum  = (int*)(dyn + 16384);
    int*                cumw = (int*)(dyn + 32768);
    unsigned long long* sel  = (unsigned long long*)(dyn + 49152);
    unsigned*           sup  = (unsigned*)dyn;                    // overlays hist+cum
    unsigned short*     clist = (unsigned short*)(dyn + 32768);   // overlays cumw

    __shared__ float sx1[KTOP], sy1[KTOP], sx2[KTOP], sy2[KTOP], sar[KTOP];
    __shared__ float sconf[KTOP];
    __shared__ unsigned char scl[KTOP];
    __shared__ int      ccnt[NCLS];
    __shared__ int      wsum[32];
    __shared__ int      s_B;
    __shared__ unsigned validw[16], keepw[16];

    int b    = blockIdx.x;
    int tid  = threadIdx.x;
    int lane = tid & 31;
    int wid  = tid >> 5;

    // ---- load per-batch histogram (built by decode) + restore it to 0 ----
    int* gh = g_hist + b * NBIN;
    #pragma unroll
    for (int i = tid; i < NBIN; i += 1024) { hist[i] = gh[i]; gh[i] = 0; }
    if (tid == 0) s_B = 0;
    if (tid < 16) { validw[tid] = 0u; keepw[tid] = 0u; }
    if (tid < NCLS) ccnt[tid] = 0;
    __syncthreads();

    // ---- descending exclusive cumsum + boundary bin ----
    {
        int hi = NBIN - 1 - 4 * tid;                // thread covers hi..hi-3 (desc)
        int h0 = hist[hi], h1 = hist[hi - 1], h2 = hist[hi - 2], h3 = hist[hi - 3];
        int s4 = h0 + h1 + h2 + h3;
        int pfx = s4;
        #pragma unroll
        for (int d = 1; d < 32; d <<= 1) {
            int v = __shfl_up_sync(0xffffffffu, pfx, d);
            if (lane >= d) pfx += v;
        }
        if (lane == 31) wsum[wid] = pfx;
        __syncthreads();
        if (tid < 32) {
            int v = wsum[lane];
            int p = v;
            #pragma unroll
            for (int d = 1; d < 32; d <<= 1) {
                int u = __shfl_up_sync(0xffffffffu, p, d);
                if (lane >= d) p += u;
            }
            wsum[lane] = p - v;                     // exclusive over warps
        }
        __syncthreads();
        int excl = wsum[wid] + (pfx - s4);          // # keys in bins > hi
        cum[hi]     = excl;                cumw[hi]     = excl;
        cum[hi - 1] = excl + h0;           cumw[hi - 1] = excl + h0;
        cum[hi - 2] = excl + h0 + h1;      cumw[hi - 2] = excl + h0 + h1;
        cum[hi - 3] = excl + h0 + h1 + h2; cumw[hi - 3] = excl + h0 + h1 + h2;
        if (excl < KTOP && excl + s4 >= KTOP) {
            int c = excl;
            if      (c + h0 >= KTOP)           s_B = hi;
            else if (c + h0 + h1 >= KTOP)      s_B = hi - 1;
            else if (c + h0 + h1 + h2 >= KTOP) s_B = hi - 2;
            else                               s_B = hi - 3;
        }
    }
    __syncthreads();
    int Bbin = s_B;

    // ---- scatter passing keys to bin-sorted slots (uint4 reads) ----
    const uint4* gk4 = (const uint4*)(g_skey + (size_t)b * NBPAD);
    for (int i4 = tid; i4 < NBPAD / 4; i4 += 1024) {
        uint4 kv = gk4[i4];
        int ib = i4 << 2;
        unsigned ks[4] = {kv.x, kv.y, kv.z, kv.w};
        #pragma unroll
        for (int u = 0; u < 4; ++u) {
            unsigned sk = ks[u];
            int i = ib + u;                          // i==NBOX pad has sk==0 -> fails
            if (sk > 0xBF000000u) {
                int bin = (sk >> 11) & 0xFFFu;
                if (bin >= Bbin) {
                    int slot = atomicAdd(&cumw[bin], 1);
                    if (slot < 1024)
                        sel[slot] = ((unsigned long long)sk << 32) |
                                    (unsigned long long)(0xFFFFFFFFu - (unsigned)i);
                }
            }
        }
    }
    __syncthreads();     // cumw dead past here; clist overlays it

    // ---- rank + gather to smem + embedded class-bucket append ----
    int C = cum[Bbin] + hist[Bbin];
    if (C > 1024) C = 1024;
    if (tid < C) {
        unsigned long long key = sel[tid];
        int bin  = (int)((key >> 43) & 0xFFFull);
        int base = cum[bin];
        int cnt  = hist[bin];
        int end  = base + cnt; if (end > 1024) end = 1024;
        int rank = base;
        for (int j = base; j < end; ++j) rank += (sel[j] > key);
        if (rank < KTOP) {
            unsigned idx = 0xFFFFFFFFu - (unsigned)(key & 0xFFFFFFFFull);
            const float4* sp = (const float4*)(g_boxes + ((size_t)b * NBOX + idx) * 8);
            float4 p0 = sp[0], p1 = sp[1];
            sx1[rank] = p0.x; sy1[rank] = p0.y; sx2[rank] = p0.z; sy2[rank] = p0.w;
            sar[rank] = (p0.z - p0.x) * (p0.w - p0.y);
            sconf[rank] = p1.x;
            int cls = (int)p1.y;
            scl[rank] = (unsigned char)cls;
            int pos = atomicAdd(&ccnt[cls], 1);
            if (pos < CCAP) clist[cls * CCAP + pos] = (unsigned short)rank;
            if (p1.x > 0.5f) atomicOr(&validw[rank >> 5], 1u << (rank & 31));
        }
    }
    __syncthreads();     // hist/cum/sel dead past here; sup overlays them

    // ---- sup rows: thread i owns row i; scan only its class bucket (j>i) ----
    if (tid < KTOP) {
        unsigned row[16];
        #pragma unroll
        for (int w = 0; w < 16; ++w) row[w] = 0u;

        int c   = scl[tid];
        int cnt = ccnt[c]; if (cnt > CCAP) cnt = CCAP;
        float x1i = sx1[tid], y1i = sy1[tid], x2i = sx2[tid], y2i = sy2[tid];
        float ai  = sar[tid];
        const unsigned short* lst = clist + c * CCAP;
        for (int k = 0; k < cnt; ++k) {
            int j = lst[k];
            if (j > tid) {
                float ix1 = fmaxf(x1i, sx1[j]);
                float iy1 = fmaxf(y1i, sy1[j]);
                float ix2 = fminf(x2i, sx2[j]);
                float iy2 = fminf(y2i, sy2[j]);
                float inter = fmaxf(ix2 - ix1, 0.0f) * fmaxf(iy2 - iy1, 0.0f);
                float iou = inter / (ai + sar[j] - inter + 1e-9f);
                if (iou > 0.3f) row[j >> 5] |= 1u << (j & 31);
            }
        }
        #pragma unroll
        for (int w = 0; w < 16; ++w) sup[tid * 16 + w] = row[w];
    }
    __syncthreads();

    // ---- chunked greedy scan (warp 0) ----
    if (tid < 32) {
        unsigned cand  = (lane < 16) ? validw[lane] : 0u;
        unsigned keepv = 0u;
        for (int blk = 0; blk < 16; ++blk) {
            unsigned cw = __shfl_sync(0xffffffffu, cand, blk);
            int base = blk << 5;
            unsigned rw = sup[(base + lane) * 16 + blk];   // row base+lane, word blk
            unsigned k32 = 0u;
            #pragma unroll 1
            for (int g = 0; g < 32; g += 8) {
                unsigned s0 = __shfl_sync(0xffffffffu, rw, g + 0);
                unsigned s1 = __shfl_sync(0xffffffffu, rw, g + 1);
                unsigned s2 = __shfl_sync(0xffffffffu, rw, g + 2);
                unsigned s3 = __shfl_sync(0xffffffffu, rw, g + 3);
                unsigned s4 = __shfl_sync(0xffffffffu, rw, g + 4);
                unsigned s5 = __shfl_sync(0xffffffffu, rw, g + 5);
                unsigned s6 = __shfl_sync(0xffffffffu, rw, g + 6);
                unsigned s7 = __shfl_sync(0xffffffffu, rw, g + 7);
                if (cw & (1u << (g + 0))) { k32 |= 1u << (g + 0); cw &= ~s0; }
                if (cw & (1u << (g + 1))) { k32 |= 1u << (g + 1); cw &= ~s1; }
                if (cw & (1u << (g + 2))) { k32 |= 1u << (g + 2); cw &= ~s2; }
                if (cw & (1u << (g + 3))) { k32 |= 1u << (g + 3); cw &= ~s3; }
                if (cw & (1u << (g + 4))) { k32 |= 1u << (g + 4); cw &= ~s4; }
                if (cw & (1u << (g + 5))) { k32 |= 1u << (g + 5); cw &= ~s5; }
                if (cw & (1u << (g + 6))) { k32 |= 1u << (g + 6); cw &= ~s6; }
                if (cw & (1u << (g + 7))) { k32 |= 1u << (g + 7); cw &= ~s7; }
            }
            // dense apply: 32 independent masked loads
            unsigned acc = 0u;
            if (lane < 16) {
                #pragma unroll
                for (int j = 0; j < 32; ++j) {
                    unsigned m = 0u - ((k32 >> j) & 1u);
                    acc |= sup[(base + j) * 16 + lane] & m;
                }
            }
            if (lane > blk && lane < 16) cand &= ~acc;
            if (lane == blk) keepv = k32;
        }
        if (lane < 16) keepw[lane] = keepv;
    }
    __syncthreads();

    // ---- coalesced output: all 7 columns from smem ----
    if (tid < KTOP) {
        float* dst = out + ((size_t)b * KTOP + tid) * 7;
        bool k = (keepw[tid >> 5] >> (tid & 31)) & 1u;
        dst[0] = sx1[tid];
        dst[1] = sy1[tid];
        dst[2] = sx2[tid];
        dst[3] = sy2[tid];
        dst[4] = sconf[tid];
        dst[5] = (float)scl[tid];
        dst[6] = k ? 1.0f : 0.0f;
    }
}

// ---------------- launch ------------------------------------------
extern "C" void kernel_launch(void* const* d_in, const int* in_sizes, int n_in,
                              void* d_out, int out_size)
{
    const float* out13 = (const float*)d_in[0];
    const float* out26 = (const float*)d_in[1];
    const float* out52 = (const float*)d_in[2];
    const float* anc13 = (const float*)d_in[3];
    const float* anc26 = (const float*)d_in[4];
    const float* anc52 = (const float*)d_in[5];
    float* out = (float*)d_out;

    const int TPB = 256;
    decode_all_kernel<<<(TTOT + TPB - 1) / TPB, TPB>>>(out13, out26, out52,
                                                       anc13, anc26, anc52);

    static bool attr_set = false;
    if (!attr_set) {
        cudaFuncSetAttribute(nms_kernel,
                             cudaFuncAttributeMaxDynamicSharedMemorySize, K2_SMEM);
        attr_set = true;
    }
    nms_kernel<<<BATCH, 1024, K2_SMEM>>>(out);
}

// round 17
// speedup vs baseline: 1.0231x; 1.0231x over previous
#include <cuda_runtime.h>
#include <stdint.h>
#include <math.h>

#define BATCH 32
#define NBOX  10647          // 507 + 2028 + 8112
#define NBPAD 10648          // padded stride (16B-aligned uint4 rows)
#define KTOP  512
#define NBIN  4096
#define NCLS  80
#define CCAP  64             // per-class bucket capacity (avg 6.4, P(>64)~0)
#define TTOT  (BATCH * 3 * (169 + 676 + 2704))
#define T13   (BATCH * 3 * 169)
#define T26   (BATCH * 3 * 676)

// ---------------- scratch (no allocation allowed) ----------------
__device__ float    g_boxes[BATCH * NBOX * 8];  // x1,y1,x2,y2,conf,cls,pad,pad
__device__ unsigned g_skey [BATCH * NBPAD];     // mono32(score); pad elem stays 0
__device__ int      g_hist [BATCH * NBIN];      // zero at rest; decode fills, nms clears

__device__ __forceinline__ float sigm(float x) {
    return 1.0f / (1.0f + expf(-x));
}

// ---------------- compile-time specialized per-scale decode -------
template <int HW, int W, int NOFF>
__device__ __forceinline__ void decode_scale(const float* __restrict__ src,
                                             const float* __restrict__ anc,
                                             int r, float t)
{
    int b    = r / (3 * HW);
    int q    = r - b * 3 * HW;
    int a    = q / HW;
    int cell = q - a * HW;
    int y    = cell / W;
    int x    = cell - y * W;

    const float* p = src + ((size_t)b * 255 + (size_t)a * 85) * HW + cell;

    float tx = __ldcs(p);
    float ty = __ldcs(p + HW);
    float tw = __ldcs(p + 2 * HW);
    float th = __ldcs(p + 3 * HW);
    float to = __ldcs(p + 4 * HW);

    // argmax over 80 classes, pairwise-tree per group of 8 (first-occurrence ties)
    const float* pc = p + 5 * HW;
    float best = -3.402823466e38f;
    int   bcls = 0;
    #pragma unroll
    for (int f = 0; f < 80; f += 8) {
        float v0 = __ldcs(pc + (f + 0) * HW);
        float v1 = __ldcs(pc + (f + 1) * HW);
        float v2 = __ldcs(pc + (f + 2) * HW);
        float v3 = __ldcs(pc + (f + 3) * HW);
        float v4 = __ldcs(pc + (f + 4) * HW);
        float v5 = __ldcs(pc + (f + 5) * HW);
        float v6 = __ldcs(pc + (f + 6) * HW);
        float v7 = __ldcs(pc + (f + 7) * HW);
        float m01v = (v1 > v0) ? v1 : v0;  int m01i = (v1 > v0) ? f + 1 : f + 0;
        float m23v = (v3 > v2) ? v3 : v2;  int m23i = (v3 > v2) ? f + 3 : f + 2;
        float m45v = (v5 > v4) ? v5 : v4;  int m45i = (v5 > v4) ? f + 5 : f + 4;
        float m67v = (v7 > v6) ? v7 : v6;  int m67i = (v7 > v6) ? f + 7 : f + 6;
        float a03v = (m23v > m01v) ? m23v : m01v;  int a03i = (m23v > m01v) ? m23i : m01i;
        float a47v = (m67v > m45v) ? m67v : m45v;  int a47i = (m67v > m45v) ? m67i : m45i;
        float gv   = (a47v > a03v) ? a47v : a03v;  int gi   = (a47v > a03v) ? a47i : a03i;
        if (gv > best) { best = gv; bcls = gi; }
    }

    float conf = sigm(to);
    float cx   = ((float)x + sigm(tx)) * t;
    float cy   = ((float)y + sigm(ty)) * t;
    float w_   = anc[a * 2 + 0] * expf(tw);
    float h_   = anc[a * 2 + 1] * expf(th);

    int n = NOFF + cell * 3 + a;
    float4* bp = (float4*)(g_boxes + ((size_t)b * NBOX + n) * 8);
    __stcs(bp,     make_float4(cx - 0.5f * w_, cy - 0.5f * h_, cx + 0.5f * w_, cy + 0.5f * h_));
    __stcs(bp + 1, make_float4(conf, (float)bcls, 0.0f, 0.0f));

    unsigned sk = (conf > 0.5f) ? (__float_as_uint(conf) | 0x80000000u) : 0x407FFFFFu;
    g_skey[(size_t)b * NBPAD + n] = sk;
    if (conf > 0.5f)
        atomicAdd(&g_hist[b * NBIN + ((sk >> 11) & 0xFFFu)], 1);
}

__global__ void __launch_bounds__(256)
decode_all_kernel(const float* __restrict__ o13, const float* __restrict__ o26,
                  const float* __restrict__ o52, const float* __restrict__ a13,
                  const float* __restrict__ a26, const float* __restrict__ a52)
{
    int gid = blockIdx.x * blockDim.x + threadIdx.x;
    if (gid >= TTOT) return;

    if (gid < T13)
        decode_scale<169, 13, 0>(o13, a13, gid, 32.0f);
    else if (gid < T13 + T26)
        decode_scale<676, 26, 507>(o26, a26, gid - T13, 16.0f);
    else
        decode_scale<2704, 52, 2535>(o52, a52, gid - T13 - T26, 8.0f);
}

// ======== fused tail: hist-load(+zero) + cumsum + scatter + rank/gather(+buckets)
//          + sup + greedy + keep-flag output ======
// dyn smem (sequential lifetimes):
//   [0,16384)      hist int[4096]     } live until end of rank
//   [16384,32768)  cum  int[4096]     }
//   [32768,49152)  cumw int[4096]     } cumw dead after scatter
//   [49152,57344)  sel  u64[1024]
//   after scatter: cls_list u16[80*64] overlays [32768,43008)
//   after rank:    sup u32[512*16] overlays [0,32768)
#define K2_SMEM 57344

__global__ void __launch_bounds__(1024, 1)
nms_kernel(float* __restrict__ out)
{
    extern __shared__ char dyn[];
    int*                hist = (int*)dyn;
    int*                cum  = (int*)(dyn + 16384);
    int*                cumw = (int*)(dyn + 32768);
    unsigned long long* sel  = (unsigned long long*)(dyn + 49152);
    unsigned*           sup  = (unsigned*)dyn;                    // overlays hist+cum
    unsigned short*     clist = (unsigned short*)(dyn + 32768);   // overlays cumw

    __shared__ float sx1[KTOP], sy1[KTOP], sx2[KTOP], sy2[KTOP], sar[KTOP];
    __shared__ unsigned char scl[KTOP];
    __shared__ int      ccnt[NCLS];
    __shared__ int      wsum[32];
    __shared__ int      s_B;
    __shared__ unsigned validw[16], keepw[16];

    int b    = blockIdx.x;
    int tid  = threadIdx.x;
    int lane = tid & 31;
    int wid  = tid >> 5;

    // ---- load per-batch histogram (built by decode) + restore it to 0 ----
    int* gh = g_hist + b * NBIN;
    #pragma unroll
    for (int i = tid; i < NBIN; i += 1024) { hist[i] = gh[i]; gh[i] = 0; }
    if (tid == 0) s_B = 0;
    if (tid < 16) { validw[tid] = 0u; keepw[tid] = 0u; }
    if (tid < NCLS) ccnt[tid] = 0;
    __syncthreads();

    // ---- descending exclusive cumsum + boundary bin ----
    {
        int hi = NBIN - 1 - 4 * tid;                // thread covers hi..hi-3 (desc)
        int h0 = hist[hi], h1 = hist[hi - 1], h2 = hist[hi - 2], h3 = hist[hi - 3];
        int s4 = h0 + h1 + h2 + h3;
        int pfx = s4;
        #pragma unroll
        for (int d = 1; d < 32; d <<= 1) {
            int v = __shfl_up_sync(0xffffffffu, pfx, d);
            if (lane >= d) pfx += v;
        }
        if (lane == 31) wsum[wid] = pfx;
        __syncthreads();
        if (tid < 32) {
            int v = wsum[lane];
            int p = v;
            #pragma unroll
            for (int d = 1; d < 32; d <<= 1) {
                int u = __shfl_up_sync(0xffffffffu, p, d);
                if (lane >= d) p += u;
            }
            wsum[lane] = p - v;                     // exclusive over warps
        }
        __syncthreads();
        int excl = wsum[wid] + (pfx - s4);          // # keys in bins > hi
        cum[hi]     = excl;                cumw[hi]     = excl;
        cum[hi - 1] = excl + h0;           cumw[hi - 1] = excl + h0;
        cum[hi - 2] = excl + h0 + h1;      cumw[hi - 2] = excl + h0 + h1;
        cum[hi - 3] = excl + h0 + h1 + h2; cumw[hi - 3] = excl + h0 + h1 + h2;
        if (excl < KTOP && excl + s4 >= KTOP) {
            int c = excl;
            if      (c + h0 >= KTOP)           s_B = hi;
            else if (c + h0 + h1 >= KTOP)      s_B = hi - 1;
            else if (c + h0 + h1 + h2 >= KTOP) s_B = hi - 2;
            else                               s_B = hi - 3;
        }
    }
    __syncthreads();
    int Bbin = s_B;

    // ---- scatter passing keys to bin-sorted slots (uint4 reads) ----
    const uint4* gk4 = (const uint4*)(g_skey + (size_t)b * NBPAD);
    for (int i4 = tid; i4 < NBPAD / 4; i4 += 1024) {
        uint4 kv = gk4[i4];
        int ib = i4 << 2;
        unsigned ks[4] = {kv.x, kv.y, kv.z, kv.w};
        #pragma unroll
        for (int u = 0; u < 4; ++u) {
            unsigned sk = ks[u];
            int i = ib + u;                          // i==NBOX pad has sk==0 -> fails
            if (sk > 0xBF000000u) {
                int bin = (sk >> 11) & 0xFFFu;
                if (bin >= Bbin) {
                    int slot = atomicAdd(&cumw[bin], 1);
                    if (slot < 1024)
                        sel[slot] = ((unsigned long long)sk << 32) |
                                    (unsigned long long)(0xFFFFFFFFu - (unsigned)i);
                }
            }
        }
    }
    __syncthreads();     // cumw dead past here; clist overlays it

    // ---- rank + gather (writes out cols 0-5 mid-kernel, hides behind later
    //      phases) + embedded class-bucket append ----
    int C = cum[Bbin] + hist[Bbin];
    if (C > 1024) C = 1024;
    if (tid < C) {
        unsigned long long key = sel[tid];
        int bin  = (int)((key >> 43) & 0xFFFull);
        int base = cum[bin];
        int cnt  = hist[bin];
        int end  = base + cnt; if (end > 1024) end = 1024;
        int rank = base;
        for (int j = base; j < end; ++j) rank += (sel[j] > key);
        if (rank < KTOP) {
            unsigned idx = 0xFFFFFFFFu - (unsigned)(key & 0xFFFFFFFFull);
            const float4* sp = (const float4*)(g_boxes + ((size_t)b * NBOX + idx) * 8);
            float4 p0 = sp[0], p1 = sp[1];
            sx1[rank] = p0.x; sy1[rank] = p0.y; sx2[rank] = p0.z; sy2[rank] = p0.w;
            sar[rank] = (p0.z - p0.x) * (p0.w - p0.y);
            int cls = (int)p1.y;
            scl[rank] = (unsigned char)cls;
            int pos = atomicAdd(&ccnt[cls], 1);
            if (pos < CCAP) clist[cls * CCAP + pos] = (unsigned short)rank;
            float* dst = out + ((size_t)b * KTOP + rank) * 7;
            dst[0] = p0.x; dst[1] = p0.y; dst[2] = p0.z; dst[3] = p0.w;
            dst[4] = p1.x; dst[5] = p1.y;
            if (p1.x > 0.5f) atomicOr(&validw[rank >> 5], 1u << (rank & 31));
        }
    }
    __syncthreads();     // hist/cum/sel dead past here; sup overlays them

    // ---- sup rows: thread i owns row i; scan only its class bucket (j>i) ----
    if (tid < KTOP) {
        unsigned row[16];
        #pragma unroll
        for (int w = 0; w < 16; ++w) row[w] = 0u;

        int c   = scl[tid];
        int cnt = ccnt[c]; if (cnt > CCAP) cnt = CCAP;
        float x1i = sx1[tid], y1i = sy1[tid], x2i = sx2[tid], y2i = sy2[tid];
        float ai  = sar[tid];
        const unsigned short* lst = clist + c * CCAP;
        for (int k = 0; k < cnt; ++k) {
            int j = lst[k];
            if (j > tid) {
                float ix1 = fmaxf(x1i, sx1[j]);
                float iy1 = fmaxf(y1i, sy1[j]);
                float ix2 = fminf(x2i, sx2[j]);
                float iy2 = fminf(y2i, sy2[j]);
                float inter = fmaxf(ix2 - ix1, 0.0f) * fmaxf(iy2 - iy1, 0.0f);
                float iou = inter / (ai + sar[j] - inter + 1e-9f);
                if (iou > 0.3f) row[j >> 5] |= 1u << (j & 31);
            }
        }
        #pragma unroll
        for (int w = 0; w < 16; ++w) sup[tid * 16 + w] = row[w];
    }
    __syncthreads();

    // ---- chunked greedy scan (warp 0) ----
    if (tid < 32) {
        unsigned cand  = (lane < 16) ? validw[lane] : 0u;
        unsigned keepv = 0u;
        for (int blk = 0; blk < 16; ++blk) {
            unsigned cw = __shfl_sync(0xffffffffu, cand, blk);
            int base = blk << 5;
            unsigned rw = sup[(base + lane) * 16 + blk];   // row base+lane, word blk
            unsigned k32 = 0u;
            #pragma unroll 1
            for (int g = 0; g < 32; g += 8) {
                unsigned s0 = __shfl_sync(0xffffffffu, rw, g + 0);
                unsigned s1 = __shfl_sync(0xffffffffu, rw, g + 1);
                unsigned s2 = __shfl_sync(0xffffffffu, rw, g + 2);
                unsigned s3 = __shfl_sync(0xffffffffu, rw, g + 3);
                unsigned s4 = __shfl_sync(0xffffffffu, rw, g + 4);
                unsigned s5 = __shfl_sync(0xffffffffu, rw, g + 5);
                unsigned s6 = __shfl_sync(0xffffffffu, rw, g + 6);
                unsigned s7 = __shfl_sync(0xffffffffu, rw, g + 7);
                if (cw & (1u << (g + 0))) { k32 |= 1u << (g + 0); cw &= ~s0; }
                if (cw & (1u << (g + 1))) { k32 |= 1u << (g + 1); cw &= ~s1; }
                if (cw & (1u << (g + 2))) { k32 |= 1u << (g + 2); cw &= ~s2; }
                if (cw & (1u << (g + 3))) { k32 |= 1u << (g + 3); cw &= ~s3; }
                if (cw & (1u << (g + 4))) { k32 |= 1u << (g + 4); cw &= ~s4; }
                if (cw & (1u << (g + 5))) { k32 |= 1u << (g + 5); cw &= ~s5; }
                if (cw & (1u << (g + 6))) { k32 |= 1u << (g + 6); cw &= ~s6; }
                if (cw & (1u << (g + 7))) { k32 |= 1u << (g + 7); cw &= ~s7; }
            }
            // dense apply: 32 independent masked loads
            unsigned acc = 0u;
            if (lane < 16) {
                #pragma unroll
                for (int j = 0; j < 32; ++j) {
                    unsigned m = 0u - ((k32 >> j) & 1u);
                    acc |= sup[(base + j) * 16 + lane] & m;
                }
            }
            if (lane > blk && lane < 16) cand &= ~acc;
            if (lane == blk) keepv = k32;
        }
        if (lane < 16) keepw[lane] = keepv;
    }
    __syncthreads();

    // ---- keep flag only (cols 0-5 already written during gather) ----
    if (tid < KTOP) {
        bool k = (keepw[tid >> 5] >> (tid & 31)) & 1u;
        out[((size_t)b * KTOP + tid) * 7 + 6] = k ? 1.0f : 0.0f;
    }
}

// ---------------- launch ------------------------------------------
extern "C" void kernel_launch(void* const* d_in, const int* in_sizes, int n_in,
                              void* d_out, int out_size)
{
    const float* out13 = (const float*)d_in[0];
    const float* out26 = (const float*)d_in[1];
    const float* out52 = (const float*)d_in[2];
    const float* anc13 = (const float*)d_in[3];
    const float* anc26 = (const float*)d_in[4];
    const float* anc52 = (const float*)d_in[5];
    float* out = (float*)d_out;

    const int TPB = 256;
    decode_all_kernel<<<(TTOT + TPB - 1) / TPB, TPB>>>(out13, out26, out52,
                                                       anc13, anc26, anc52);

    static bool attr_set = false;
    if (!attr_set) {
        cudaFuncSetAttribute(nms_kernel,
                             cudaFuncAttributeMaxDynamicSharedMemorySize, K2_SMEM);
        attr_set = true;
    }
    nms_kernel<<<BATCH, 1024, K2_SMEM>>>(out);
}